// round 9
// baseline (speedup 1.0000x reference)
#include <cuda_runtime.h>
#include <math.h>

#define G        512
#define S        32
#define PTS      8
#define SEGS_PER (PTS - 1)           // 7
#define NSEG     (S * SEGS_PER)      // 224
#define SUBT     16                  // cull/render granularity (16x16 px)
#define REGION   32                  // CTA covers 32x32 px = 4 subtiles
#define NTHREADS 512                 // 4 groups x 128 threads
#define NCTA     (G / REGION)        // 16 -> 256 CTAs

// ---------------------------------------------------------------------------
// 256 CTAs x 512 threads; each CTA owns a 32x32 region split into four 16x16
// subtiles, one per 128-thread group (warps 0-3 -> sub 0, 4-7 -> sub 1, ...).
// Stage: 128 threads load ALL stroke points (128 x LDG.128), clamp*512 into
//        SMEM once per CTA; 32 threads load thicknesses -> {r, 1/(4t^2)}.
// Cull:  each group capsule-culls all 224 segments vs ITS subtile center
//        (same granularity & total evals as the 1024-CTA version), ballot-
//        compacting survivors into its own SMEM list.
// Render: within each group, 2 horizontally adjacent pixels per thread; min
//        of scaled squared distance; one sqrt; one float2 store.
// ---------------------------------------------------------------------------
__global__ void __launch_bounds__(NTHREADS)
render_kernel(const float* __restrict__ strokes,
              const float* __restrict__ thick,
              float* __restrict__ out) {
    __shared__ float  s_pts[S * PTS * 2];    // clamped * 512 coords
    __shared__ float2 s_t[S];                // {r = 2t, sc = 1/(4t^2)}
    __shared__ float4 s_a[4][NSEG];          // per-subtile: vx, vy, ex, ey
    __shared__ float2 s_b[4][NSEG];          // per-subtile: invd2, sc
    __shared__ int    s_n[4];

    const int tid  = threadIdx.x;
    const int lane = tid & 31;

    // ---- Stage inputs once per CTA ----
    if (tid < 128) {
        float4 v = ((const float4*)strokes)[tid];
        float4 c;
        c.x = __saturatef(v.x) * (float)G;
        c.y = __saturatef(v.y) * (float)G;
        c.z = __saturatef(v.z) * (float)G;
        c.w = __saturatef(v.w) * (float)G;
        ((float4*)s_pts)[tid] = c;
    }
    if (tid < S) {
        float t = fmaxf(fmaf(thick[tid], 2.0f, 0.5f), 0.5f);
        float r = 2.0f * t;
        s_t[tid] = make_float2(r, __fdividef(1.0f, r * r));
    }
    if (tid < 4) s_n[tid] = 0;
    __syncthreads();

    const int ti = blockIdx.y * REGION;      // region row base (out stride G)
    const int tj = blockIdx.x * REGION;      // region col base (contiguous)

    const int sub = tid >> 7;                // subtile 0..3
    const int lt  = tid & 127;               // lane within group
    const int sx  = ti + (sub >> 1) * SUBT;  // subtile row base
    const int sy  = tj + (sub & 1) * SUBT;   // subtile col base

    const float cx   = (float)sx + (SUBT - 1) * 0.5f;
    const float cy   = (float)sy + (SUBT - 1) * 0.5f;
    const float RMAX = (SUBT - 1) * 0.5f * 1.41421356f + 1.0f;

    // ---- Cull: each group evaluates all 224 segments vs its subtile ----
    #define CULL(SEG)                                                         \
    {                                                                         \
        const int s    = ((SEG) * 9363) >> 16;          /* seg / 7 */         \
        const int base = ((SEG) + s) * 2;               /* (s*PTS+k)*2 */     \
        float2 vv = *(const float2*)(s_pts + base);                           \
        float2 ww = *(const float2*)(s_pts + base + 2);                       \
        float ex = ww.x - vv.x;                                               \
        float ey = ww.y - vv.y;                                               \
        float d2 = ex * ex + ey * ey;                                         \
        float invd2 = __fdividef(1.0f, d2 + 1e-5f);                           \
        float2 rs = s_t[s];                                                   \
        float dx  = cx - vv.x;                                                \
        float dy  = cy - vv.y;                                                \
        float dot = dx * ex + dy * ey;                                        \
        float fr  = __saturatef(dot * invd2);                                 \
        float ddx = fmaf(-fr, ex, dx);                                        \
        float ddy = fmaf(-fr, ey, dy);                                        \
        float dq  = ddx * ddx + ddy * ddy;                                    \
        float thr = rs.x + RMAX;                                              \
        bool keep = (dq <= thr * thr);                                        \
        unsigned bal = __ballot_sync(0xffffffffu, keep);                      \
        int basep = 0;                                                        \
        if (lane == 0 && bal) basep = atomicAdd(&s_n[sub], __popc(bal));      \
        basep = __shfl_sync(0xffffffffu, basep, 0);                           \
        if (keep) {                                                           \
            int p = basep + __popc(bal & ((1u << lane) - 1u));                \
            s_a[sub][p] = make_float4(vv.x, vv.y, ex, ey);                    \
            s_b[sub][p] = make_float2(invd2, rs.y);                           \
        }                                                                     \
    }

    CULL(lt);
    if (lt < NSEG - 128) CULL(128 + lt);     // lt < 96: full warps 0..2 of group
    #undef CULL

    __syncthreads();

    // ---- Render: 2 horizontally adjacent pixels per thread ----
    const int tx = lt & 7;                   // px cols 2tx, 2tx+1
    const int ty = lt >> 3;                  // row 0..15
    const float px  = (float)(sx + ty);
    const float py0 = (float)(sy + 2 * tx);
    const int n = s_n[sub];

    const float4* __restrict__ la = s_a[sub];
    const float2* __restrict__ lb = s_b[sub];

    float m0 = 1e30f;
    float m1 = 1e30f;
    #pragma unroll 2
    for (int q = 0; q < n; q++) {
        float4 a = la[q];
        float2 b = lb[q];
        float dx   = px - a.x;
        float dy0  = py0 - a.y;
        float dy1  = dy0 + 1.0f;
        float dxez = dx * a.z;
        float dot0 = fmaf(dy0, a.w, dxez);
        float dot1 = dot0 + a.w;
        float fr0  = __saturatef(dot0 * b.x);
        float fr1  = __saturatef(dot1 * b.x);
        float ddx0 = fmaf(-fr0, a.z, dx);
        float ddy0 = fmaf(-fr0, a.w, dy0);
        float ddx1 = fmaf(-fr1, a.z, dx);
        float ddy1 = fmaf(-fr1, a.w, dy1);
        float dq0  = fmaf(ddx0, ddx0, ddy0 * ddy0);
        float dq1  = fmaf(ddx1, ddx1, ddy1 * ddy1);
        m0 = fminf(m0, dq0 * b.y);
        m1 = fminf(m1, dq1 * b.y);
    }

    float2 res = make_float2(fminf(sqrtf(m0), 1.0f), fminf(sqrtf(m1), 1.0f));
    *(float2*)(out + (sx + ty) * G + (sy + 2 * tx)) = res;
}

extern "C" void kernel_launch(void* const* d_in, const int* in_sizes, int n_in,
                              void* d_out, int out_size) {
    // metadata order: strokes [32,8,2] f32 (512 elems), thicknesses [32] f32.
    const float* strokes = (const float*)d_in[0];
    const float* thick   = (const float*)d_in[1];
    if (n_in >= 2 && in_sizes[0] == S && in_sizes[1] == S * PTS * 2) {
        strokes = (const float*)d_in[1];
        thick   = (const float*)d_in[0];
    }
    float* out = (float*)d_out;

    dim3 block(NTHREADS);
    dim3 grid(NCTA, NCTA);
    render_kernel<<<grid, block>>>(strokes, thick, out);
}

// round 10
// speedup vs baseline: 1.0036x; 1.0036x over previous
#include <cuda_runtime.h>
#include <math.h>

#define G        512
#define S        32
#define PTS      8
#define SEGS_PER (PTS - 1)           // 7
#define NSEG     (S * SEGS_PER)      // 224
#define WTILE    8                   // 8x8 px per warp
#define WARPS    8                   // warps per CTA
#define NTHREADS (WARPS * 32)        // 256
#define TPRW     (G / WTILE)         // 64 warp-tiles per row
#define NTILES_W (TPRW * TPRW)       // 4096
#define NCTA     (NTILES_W / WARPS)  // 512

// ---------------------------------------------------------------------------
// Warp-autonomous renderer: 512 CTAs x 8 warps; each warp owns one 8x8 pixel
// tile end-to-end. One CTA barrier total (after input staging); afterwards
// warps never synchronize with each other.
// Stage:  128 threads LDG.128 all stroke points, clamp*512 -> SMEM;
//         32 threads build per-stroke {r=2t, sc=1/(4t^2)}.
// Cull:   exactly 7 ballot rounds (seg = r*32+lane, 224=7*32), survivors
//         compacted into a warp-private SMEM list; base index kept in
//         registers (lane-uniform popc) - no atomics, no shuffles.
// Render: 2 horizontally adjacent pixels per lane (64 px/warp); min of
//         scaled squared distance; one sqrt; one float2 store.
// ---------------------------------------------------------------------------
__global__ void __launch_bounds__(NTHREADS)
render_kernel(const float* __restrict__ strokes,
              const float* __restrict__ thick,
              float* __restrict__ out) {
    __shared__ float  s_pts[S * PTS * 2];       // clamped * 512 coords
    __shared__ float2 s_t[S];                   // {r = 2t, sc = 1/(4t^2)}
    __shared__ float4 s_a[WARPS][NSEG];         // survivors: vx, vy, ex, ey
    __shared__ float2 s_b[WARPS][NSEG];         // survivors: invd2, sc

    const int tid  = threadIdx.x;
    const int lane = tid & 31;
    const int wrp  = tid >> 5;

    // ---- Stage inputs once per CTA ----
    if (tid < 128) {
        float4 v = ((const float4*)strokes)[tid];
        float4 c;
        c.x = __saturatef(v.x) * (float)G;
        c.y = __saturatef(v.y) * (float)G;
        c.z = __saturatef(v.z) * (float)G;
        c.w = __saturatef(v.w) * (float)G;
        ((float4*)s_pts)[tid] = c;
    }
    if (tid < S) {
        float t = fmaxf(fmaf(thick[tid], 2.0f, 0.5f), 0.5f);
        float r = 2.0f * t;
        s_t[tid] = make_float2(r, __fdividef(1.0f, r * r));
    }
    __syncthreads();                            // the only CTA-wide barrier

    // ---- Warp tile coordinates ----
    const int wtile = blockIdx.x * WARPS + wrp; // 0..4095
    const int ti = (wtile >> 6) * WTILE;        // row base (out stride G)
    const int tj = (wtile & (TPRW - 1)) * WTILE;// col base (contiguous)

    const float cx   = (float)ti + (WTILE - 1) * 0.5f;
    const float cy   = (float)tj + (WTILE - 1) * 0.5f;
    const float RMAX = (WTILE - 1) * 0.5f * 1.41421356f + 1.0f;

    float4* __restrict__ la = s_a[wrp];
    float2* __restrict__ lb = s_b[wrp];

    // ---- Cull: 7 rounds, warp-private compaction, no atomics ----
    int nsurv = 0;
    #pragma unroll
    for (int r = 0; r < SEGS_PER; r++) {
        const int seg  = r * 32 + lane;
        const int s    = (seg * 9363) >> 16;    // seg / 7
        const int base = (seg + s) * 2;         // (s*PTS + k)*2
        float2 vv = *(const float2*)(s_pts + base);
        float2 ww = *(const float2*)(s_pts + base + 2);

        float ex = ww.x - vv.x;
        float ey = ww.y - vv.y;
        float d2 = ex * ex + ey * ey;
        float invd2 = __fdividef(1.0f, d2 + 1e-5f);
        float2 rs = s_t[s];

        float dx  = cx - vv.x;
        float dy  = cy - vv.y;
        float dot = dx * ex + dy * ey;
        float fr  = __saturatef(dot * invd2);
        float ddx = fmaf(-fr, ex, dx);
        float ddy = fmaf(-fr, ey, dy);
        float dq  = ddx * ddx + ddy * ddy;
        float thr = rs.x + RMAX;
        bool keep = (dq <= thr * thr);

        unsigned bal = __ballot_sync(0xffffffffu, keep);
        if (keep) {
            int p = nsurv + __popc(bal & ((1u << lane) - 1u));
            la[p] = make_float4(vv.x, vv.y, ex, ey);
            lb[p] = make_float2(invd2, rs.y);
        }
        nsurv += __popc(bal);                   // lane-uniform
    }
    __syncwarp();

    // ---- Render: 2 horizontally adjacent pixels per lane ----
    const int row = lane >> 2;                  // 0..7
    const int cp  = (lane & 3) * 2;             // px cols cp, cp+1
    const float px  = (float)(ti + row);
    const float py0 = (float)(tj + cp);

    float m0 = 1e30f;
    float m1 = 1e30f;
    #pragma unroll 2
    for (int q = 0; q < nsurv; q++) {
        float4 a = la[q];
        float2 b = lb[q];
        float dx   = px - a.x;
        float dy0  = py0 - a.y;
        float dy1  = dy0 + 1.0f;
        float dxez = dx * a.z;
        float dot0 = fmaf(dy0, a.w, dxez);
        float dot1 = dot0 + a.w;
        float fr0  = __saturatef(dot0 * b.x);
        float fr1  = __saturatef(dot1 * b.x);
        float ddx0 = fmaf(-fr0, a.z, dx);
        float ddy0 = fmaf(-fr0, a.w, dy0);
        float ddx1 = fmaf(-fr1, a.z, dx);
        float ddy1 = fmaf(-fr1, a.w, dy1);
        float dq0  = fmaf(ddx0, ddx0, ddy0 * ddy0);
        float dq1  = fmaf(ddx1, ddx1, ddy1 * ddy1);
        m0 = fminf(m0, dq0 * b.y);
        m1 = fminf(m1, dq1 * b.y);
    }

    float2 res = make_float2(fminf(sqrtf(m0), 1.0f), fminf(sqrtf(m1), 1.0f));
    *(float2*)(out + (ti + row) * G + (tj + cp)) = res;
}

extern "C" void kernel_launch(void* const* d_in, const int* in_sizes, int n_in,
                              void* d_out, int out_size) {
    // metadata order: strokes [32,8,2] f32 (512 elems), thicknesses [32] f32.
    const float* strokes = (const float*)d_in[0];
    const float* thick   = (const float*)d_in[1];
    if (n_in >= 2 && in_sizes[0] == S && in_sizes[1] == S * PTS * 2) {
        strokes = (const float*)d_in[1];
        thick   = (const float*)d_in[0];
    }
    float* out = (float*)d_out;

    render_kernel<<<NCTA, NTHREADS>>>(strokes, thick, out);
}